// round 2
// baseline (speedup 1.0000x reference)
#include <cuda_runtime.h>
#include <cuda_bf16.h>

// GraphConv: out[c] = b + sum_{e:(r,c)} 1/sqrt(d[c]*d[r]) * (x[r] @ W^T)
// Restructured: transform features BEFORE the scatter (linear commutes with
// the weighted sum). NOTE: edge_index arrives as int32 (JAX x64-disabled
// downgrades int64 silently) — previous round read long long and trapped.

#define NMAX 50000
#define F 64

__device__ float g_xw[(size_t)NMAX * F];  // x @ W^T
__device__ int   g_deg[NMAX];             // destination (col) degrees

// ---------------------------------------------------------------------------
// K0: zero degrees, xw = x @ W^T, out = bias. 256 thr/block = 4 rows.
// W stored TRANSPOSED in smem (sWt[k][j]) so lane-consecutive j is
// bank-conflict-free; x row staged in smem (pure broadcast reads).
// ---------------------------------------------------------------------------
__global__ void k_init(const float* __restrict__ x,
                       const float* __restrict__ Ww,
                       const float* __restrict__ Wb,
                       float* __restrict__ out, int n) {
    __shared__ float sWt[F * F];
    __shared__ float sx[4 * F];
    __shared__ float sb[F];

    for (int i = threadIdx.x; i < F * F; i += 256) {
        int j = i >> 6, k = i & (F - 1);      // Ww[j][k] -> sWt[k][j]
        sWt[k * F + j] = Ww[i];
    }
    if (threadIdx.x < F) sb[threadIdx.x] = Wb[threadIdx.x];

    int tid = blockIdx.x * 256 + threadIdx.x;
    if (tid < n) g_deg[tid] = 0;              // grid*256 = 3.2M >= n

    int row0 = blockIdx.x * 4;
    int gidx = row0 * F + threadIdx.x;        // 4 rows * 64 = 256 floats
    if (gidx < n * F) sx[threadIdx.x] = x[gidx];
    __syncthreads();

    int rl  = threadIdx.x >> 6;               // 0..3 local row
    int j   = threadIdx.x & (F - 1);
    int row = row0 + rl;
    if (row < n) {
        const float* xr = sx + rl * F;
        float s = 0.f;
#pragma unroll
        for (int k = 0; k < F; k++) s = fmaf(xr[k], sWt[k * F + j], s);
        g_xw[(size_t)row * F + j] = s;
        out [(size_t)row * F + j] = sb[j];
    }
}

// ---------------------------------------------------------------------------
// K1: destination-degree histogram (int RED on 50k counters)
// ---------------------------------------------------------------------------
__global__ void k_deg(const int* __restrict__ ei, int E) {
    int e = blockIdx.x * blockDim.x + threadIdx.x;
    if (e < E) atomicAdd(&g_deg[__ldg(ei + E + e)], 1);
}

// ---------------------------------------------------------------------------
// K2: 2 edges per warp, 16 lanes each. Leader lane loads (r, c, degrees),
// broadcasts via shfl; each lane does one float4 gather + one v4 RED.
// ---------------------------------------------------------------------------
__global__ void k_scatter(const int* __restrict__ ei,
                          float* __restrict__ out, int E) {
    int idx  = blockIdx.x * blockDim.x + threadIdx.x;
    int lane = idx & 31;
    int sub  = lane >> 4;                     // which edge in this warp
    int l16  = lane & 15;                     // lane within edge group
    int e    = ((idx >> 5) << 1) + sub;
    bool valid = e < E;
    int ec = valid ? e : E - 1;

    int r = 0, c = 0; float v = 0.f;
    if (l16 == 0) {
        r = __ldg(ei + ec);
        c = __ldg(ei + (size_t)E + ec);
        int dr = g_deg[r];
        int dc = g_deg[c];                    // >= 1 for any real edge
        v = (dr > 0) ? rsqrtf((float)dr * (float)dc) : 0.f;
    }
    r = __shfl_sync(0xFFFFFFFFu, r, 0, 16);
    c = __shfl_sync(0xFFFFFFFFu, c, 0, 16);
    v = __shfl_sync(0xFFFFFFFFu, v, 0, 16);
    if (!valid || v == 0.f) return;

    float4 m = ((const float4*)(g_xw + ((size_t)r << 6)))[l16];
    float4 val = make_float4(v * m.x, v * m.y, v * m.z, v * m.w);
    atomicAdd(((float4*)(out + ((size_t)c << 6))) + l16, val);
}

extern "C" void kernel_launch(void* const* d_in, const int* in_sizes, int n_in,
                              void* d_out, int out_size) {
    const float* x  = (const float*)d_in[0];
    // d_in[1] = x0, unused (use_init=False)
    const int*   ei = (const int*)d_in[2];    // int32! (JAX x64 disabled)
    const float* Ww = (const float*)d_in[3];
    const float* Wb = (const float*)d_in[4];
    float*       out = (float*)d_out;

    int n = in_sizes[0] / F;                  // 50000
    int E = in_sizes[2] / 2;                  // 800000

    k_init<<<(n + 3) / 4, 256>>>(x, Ww, Wb, out, n);
    k_deg<<<(E + 255) / 256, 256>>>(ei, E);
    long long warps = ((long long)E + 1) / 2;
    long long thr   = warps * 32;
    k_scatter<<<(unsigned)((thr + 255) / 256), 256>>>(ei, out, E);
}

// round 3
// speedup vs baseline: 2.2143x; 2.2143x over previous
#include <cuda_runtime.h>
#include <cuda_bf16.h>

// GraphConv: out[c] = b + sum_{e:(r,c)} 1/sqrt(d[c]*d[r]) * (x[r] @ W^T)
// Transform-then-scatter. R3: register-blocked k_init (8 outputs/thread) to
// kill the LDS-issue bottleneck that made R2's k_init 208us.

#define NMAX 50000
#define F 64

__device__ float g_xw[(size_t)NMAX * F];  // x @ W^T
__device__ int   g_deg[NMAX];             // destination (col) degrees
__device__ float g_rsq[NMAX];             // rsqrt(deg) or 0

// ---------------------------------------------------------------------------
// K0: zero degrees, xw = x @ W^T, out = bias.
// 256 thr/block = 32 rows; thread = (rloc = tid>>3, tj = tid&7) computes
// outputs j = tj*8 .. tj*8+7 for row rloc. W transposed in smem, row stride
// 68 floats (16B-aligned, bank-spread); x rows in smem, stride 68.
// ---------------------------------------------------------------------------
__global__ __launch_bounds__(256) void k_init(const float* __restrict__ x,
                       const float* __restrict__ Ww,
                       const float* __restrict__ Wb,
                       float* __restrict__ out, int n) {
    __shared__ float sWt[F * 68];      // sWt[k*68 + j] = Ww[j*64 + k]
    __shared__ float sx [32 * 68];     // sx[rloc*68 + k]
    __shared__ float sb [F];

    // Load + transpose W
    for (int i = threadIdx.x; i < F * F; i += 256) {
        int j = i >> 6, k = i & (F - 1);
        sWt[k * 68 + j] = Ww[i];
    }
    if (threadIdx.x < F) sb[threadIdx.x] = Wb[threadIdx.x];

    // Zero degree counters (grid covers >= n threads)
    int gtid = blockIdx.x * 256 + threadIdx.x;
    if (gtid < n) g_deg[gtid] = 0;

    // Stage 32 rows of x (coalesced gmem, conflict-free STS)
    int row0 = blockIdx.x * 32;
#pragma unroll
    for (int u = 0; u < 8; u++) {
        int i = threadIdx.x + u * 256;         // 0..2047
        int r = i >> 6, k = i & (F - 1);
        float v = (row0 + r < n) ? x[(size_t)(row0 + r) * F + k] : 0.f;
        sx[r * 68 + k] = v;
    }
    __syncthreads();

    int rloc = threadIdx.x >> 3;               // 0..31
    int tj   = threadIdx.x & 7;                // 0..7
    int row  = row0 + rloc;

    float acc[8];
#pragma unroll
    for (int u = 0; u < 8; u++) acc[u] = 0.f;

    const float* wp = sWt + tj * 8;
    const float* xp = sx + rloc * 68;
#pragma unroll
    for (int k = 0; k < F; k += 4) {
        float4 xv = *(const float4*)(xp + k);
#pragma unroll
        for (int kk = 0; kk < 4; kk++) {
            float xs = (kk == 0) ? xv.x : (kk == 1) ? xv.y : (kk == 2) ? xv.z : xv.w;
            float4 w0 = *(const float4*)(wp + (k + kk) * 68);
            float4 w1 = *(const float4*)(wp + (k + kk) * 68 + 4);
            acc[0] = fmaf(xs, w0.x, acc[0]);
            acc[1] = fmaf(xs, w0.y, acc[1]);
            acc[2] = fmaf(xs, w0.z, acc[2]);
            acc[3] = fmaf(xs, w0.w, acc[3]);
            acc[4] = fmaf(xs, w1.x, acc[4]);
            acc[5] = fmaf(xs, w1.y, acc[5]);
            acc[6] = fmaf(xs, w1.z, acc[6]);
            acc[7] = fmaf(xs, w1.w, acc[7]);
        }
    }

    if (row < n) {
        size_t base = (size_t)row * F + tj * 8;
        *(float4*)(g_xw + base)     = make_float4(acc[0], acc[1], acc[2], acc[3]);
        *(float4*)(g_xw + base + 4) = make_float4(acc[4], acc[5], acc[6], acc[7]);
        float4 b0 = *(const float4*)(sb + tj * 8);
        float4 b1 = *(const float4*)(sb + tj * 8 + 4);
        *(float4*)(out + base)     = b0;
        *(float4*)(out + base + 4) = b1;
    }
}

// ---------------------------------------------------------------------------
// K1: destination-degree histogram
// ---------------------------------------------------------------------------
__global__ void k_deg(const int* __restrict__ ei, int E) {
    int e = blockIdx.x * blockDim.x + threadIdx.x;
    if (e < E) atomicAdd(&g_deg[__ldg(ei + E + e)], 1);
}

// ---------------------------------------------------------------------------
// K1b: rsqrt(deg), 0 for isolated-as-destination nodes
// ---------------------------------------------------------------------------
__global__ void k_rsq(int n) {
    int i = blockIdx.x * blockDim.x + threadIdx.x;
    if (i < n) {
        int d = g_deg[i];
        g_rsq[i] = (d > 0) ? rsqrtf((float)d) : 0.f;
    }
}

// ---------------------------------------------------------------------------
// K2: 2 edges per warp, 16 lanes each. Leader lane loads (r, c, rsq),
// broadcasts via shfl; each lane does one float4 gather + one v4 RED.
// ---------------------------------------------------------------------------
__global__ void k_scatter(const int* __restrict__ ei,
                          float* __restrict__ out, int E) {
    int idx  = blockIdx.x * blockDim.x + threadIdx.x;
    int lane = idx & 31;
    int sub  = lane >> 4;
    int l16  = lane & 15;
    int e    = ((idx >> 5) << 1) + sub;
    bool valid = e < E;
    int ec = valid ? e : E - 1;

    int r = 0, c = 0; float v = 0.f;
    if (l16 == 0) {
        r = __ldg(ei + ec);
        c = __ldg(ei + (size_t)E + ec);
        v = g_rsq[r] * g_rsq[c];
    }
    r = __shfl_sync(0xFFFFFFFFu, r, 0, 16);
    c = __shfl_sync(0xFFFFFFFFu, c, 0, 16);
    v = __shfl_sync(0xFFFFFFFFu, v, 0, 16);
    if (!valid || v == 0.f) return;

    float4 m = ((const float4*)(g_xw + ((size_t)r << 6)))[l16];
    float4 val = make_float4(v * m.x, v * m.y, v * m.z, v * m.w);
    atomicAdd(((float4*)(out + ((size_t)c << 6))) + l16, val);
}

extern "C" void kernel_launch(void* const* d_in, const int* in_sizes, int n_in,
                              void* d_out, int out_size) {
    const float* x  = (const float*)d_in[0];
    // d_in[1] = x0, unused (use_init=False)
    const int*   ei = (const int*)d_in[2];    // int32 (JAX x64 disabled)
    const float* Ww = (const float*)d_in[3];
    const float* Wb = (const float*)d_in[4];
    float*       out = (float*)d_out;

    int n = in_sizes[0] / F;                  // 50000
    int E = in_sizes[2] / 2;                  // 800000

    k_init<<<(n + 31) / 32, 256>>>(x, Ww, Wb, out, n);
    k_deg<<<(E + 255) / 256, 256>>>(ei, E);
    k_rsq<<<(n + 255) / 256, 256>>>(n);
    long long warps = ((long long)E + 1) / 2;
    long long thr   = warps * 32;
    k_scatter<<<(unsigned)((thr + 255) / 256), 256>>>(ei, out, E);
}

// round 7
// speedup vs baseline: 2.4623x; 1.1120x over previous
#include <cuda_runtime.h>
#include <cuda_bf16.h>

// GraphConv: out[c] = b + sum_{e:(r,c)} 1/sqrt(d[c]*d[r]) * (x[r] @ W^T)
// R7 = identical resubmit of R4/R5/R6 (three infra failures in a row; the
// counting-sort design has not yet been measured).
// Pipeline: k_init (xw) -> k_deg -> k_scan1/k_scan2 (CSC offsets, rsq)
//           -> k_place (bucket edges, packed (src,val) float2)
//           -> k_gather (2 nodes/warp, register accumulate, no float atomics)

#define NMAX 50000
#define EMAX 800000
#define F 64
#define NB_MAX 256   // max scan blocks (50000/256 = 196)

__device__ float  g_xw[(size_t)NMAX * F];   // x @ W^T
__device__ int    g_deg[NMAX];              // destination degrees
__device__ float  g_rsq[NMAX];              // rsqrt(deg) or 0
__device__ int    g_loc[NMAX];              // block-local exclusive prefix
__device__ int    g_bsum[NB_MAX];           // per-scan-block totals
__device__ int    g_base[NB_MAX];           // exclusive scan of g_bsum
__device__ int    g_cnt[NMAX];              // placement cursors
__device__ float2 g_edge[EMAX];             // dest-sorted (src_as_float, val)

// ---------------------------------------------------------------------------
// K0: xw = x @ W^T; zero deg + cnt. 256 thr = 32 rows, 8 outputs/thread.
// ---------------------------------------------------------------------------
__global__ __launch_bounds__(256) void k_init(const float* __restrict__ x,
                       const float* __restrict__ Ww, int n) {
    __shared__ float sWt[F * 68];
    __shared__ float sx [32 * 68];

    for (int i = threadIdx.x; i < F * F; i += 256) {
        int j = i >> 6, k = i & (F - 1);
        sWt[k * 68 + j] = Ww[i];
    }

    int gtid = blockIdx.x * 256 + threadIdx.x;
    if (gtid < n) { g_deg[gtid] = 0; g_cnt[gtid] = 0; }

    int row0 = blockIdx.x * 32;
#pragma unroll
    for (int u = 0; u < 8; u++) {
        int i = threadIdx.x + u * 256;
        int r = i >> 6, k = i & (F - 1);
        float v = (row0 + r < n) ? x[(size_t)(row0 + r) * F + k] : 0.f;
        sx[r * 68 + k] = v;
    }
    __syncthreads();

    int rloc = threadIdx.x >> 3;
    int tj   = threadIdx.x & 7;
    int row  = row0 + rloc;

    float acc[8];
#pragma unroll
    for (int u = 0; u < 8; u++) acc[u] = 0.f;

    const float* wp = sWt + tj * 8;
    const float* xp = sx + rloc * 68;
#pragma unroll
    for (int k = 0; k < F; k += 4) {
        float4 xv = *(const float4*)(xp + k);
#pragma unroll
        for (int kk = 0; kk < 4; kk++) {
            float xs = (kk == 0) ? xv.x : (kk == 1) ? xv.y : (kk == 2) ? xv.z : xv.w;
            float4 w0 = *(const float4*)(wp + (k + kk) * 68);
            float4 w1 = *(const float4*)(wp + (k + kk) * 68 + 4);
            acc[0] = fmaf(xs, w0.x, acc[0]);  acc[1] = fmaf(xs, w0.y, acc[1]);
            acc[2] = fmaf(xs, w0.z, acc[2]);  acc[3] = fmaf(xs, w0.w, acc[3]);
            acc[4] = fmaf(xs, w1.x, acc[4]);  acc[5] = fmaf(xs, w1.y, acc[5]);
            acc[6] = fmaf(xs, w1.z, acc[6]);  acc[7] = fmaf(xs, w1.w, acc[7]);
        }
    }

    if (row < n) {
        size_t base = (size_t)row * F + tj * 8;
        *(float4*)(g_xw + base)     = make_float4(acc[0], acc[1], acc[2], acc[3]);
        *(float4*)(g_xw + base + 4) = make_float4(acc[4], acc[5], acc[6], acc[7]);
    }
}

// ---------------------------------------------------------------------------
// K1: destination-degree histogram
// ---------------------------------------------------------------------------
__global__ void k_deg(const int* __restrict__ ei, int E) {
    int e = blockIdx.x * blockDim.x + threadIdx.x;
    if (e < E) atomicAdd(&g_deg[__ldg(ei + E + e)], 1);
}

// ---------------------------------------------------------------------------
// K2a: block-level exclusive scan of degrees (256/block) + rsq
// ---------------------------------------------------------------------------
__global__ __launch_bounds__(256) void k_scan1(int n) {
    __shared__ int s[256];
    int t = threadIdx.x;
    int i = blockIdx.x * 256 + t;
    int d = (i < n) ? g_deg[i] : 0;
    s[t] = d;
    __syncthreads();
#pragma unroll
    for (int off = 1; off < 256; off <<= 1) {
        int v = (t >= off) ? s[t - off] : 0;
        __syncthreads();
        s[t] += v;
        __syncthreads();
    }
    int incl = s[t];
    if (i < n) {
        g_loc[i] = incl - d;
        g_rsq[i] = (d > 0) ? rsqrtf((float)d) : 0.f;
    }
    if (t == 255) g_bsum[blockIdx.x] = incl;
}

// ---------------------------------------------------------------------------
// K2b: exclusive scan of per-block totals (single block)
// ---------------------------------------------------------------------------
__global__ __launch_bounds__(256) void k_scan2(int nb) {
    __shared__ int s[256];
    int t = threadIdx.x;
    int d = (t < nb) ? g_bsum[t] : 0;
    s[t] = d;
    __syncthreads();
#pragma unroll
    for (int off = 1; off < 256; off <<= 1) {
        int v = (t >= off) ? s[t - off] : 0;
        __syncthreads();
        s[t] += v;
        __syncthreads();
    }
    if (t < nb) g_base[t] = s[t] - d;
}

// ---------------------------------------------------------------------------
// K3: place edges into destination buckets: (src, val) packed float2
// ---------------------------------------------------------------------------
__global__ void k_place(const int* __restrict__ ei, int E) {
    int e = blockIdx.x * blockDim.x + threadIdx.x;
    if (e >= E) return;
    int r = __ldg(ei + e);
    int c = __ldg(ei + (size_t)E + e);
    float v = g_rsq[r] * g_rsq[c];
    int pos = g_loc[c] + g_base[c >> 8] + atomicAdd(&g_cnt[c], 1);
    g_edge[pos] = make_float2(__int_as_float(r), v);
}

// ---------------------------------------------------------------------------
// K4: pull-mode gather. 2 nodes/warp, 16 lanes x float4 = 256B row.
// Batch 16 edge records per half-warp, broadcast via width-16 shfl.
// out[c] = bias + sum v * xw[r]. No float atomics anywhere.
// ---------------------------------------------------------------------------
__global__ __launch_bounds__(256) void k_gather(const float* __restrict__ Wb,
                                                float* __restrict__ out, int n) {
    int idx  = blockIdx.x * 256 + threadIdx.x;
    int sub  = (idx >> 4) & 1;                 // half-warp id
    int l16  = idx & 15;
    int c    = ((idx >> 5) << 1) + sub;        // node (uniform per half-warp)
    if (c >= n) return;
    unsigned hm = 0xFFFFu << (sub << 4);       // half-warp mask

    int off = g_loc[c] + g_base[c >> 8];
    int dc  = g_deg[c];

    float4 acc = __ldg((const float4*)Wb + l16);   // bias

    for (int base = 0; base < dc; base += 16) {
        int j = base + l16;
        float2 ev = (j < dc) ? __ldg(g_edge + off + j) : make_float2(0.f, 0.f);
        int cnt = dc - base; if (cnt > 16) cnt = 16;
#pragma unroll 4
        for (int t = 0; t < cnt; t++) {
            int   rt = __shfl_sync(hm, __float_as_int(ev.x), t, 16);
            float vt = __shfl_sync(hm, ev.y, t, 16);
            float4 m = __ldg((const float4*)(g_xw + ((size_t)rt << 6)) + l16);
            acc.x = fmaf(vt, m.x, acc.x);
            acc.y = fmaf(vt, m.y, acc.y);
            acc.z = fmaf(vt, m.z, acc.z);
            acc.w = fmaf(vt, m.w, acc.w);
        }
    }

    ((float4*)(out + ((size_t)c << 6)))[l16] = acc;
}

extern "C" void kernel_launch(void* const* d_in, const int* in_sizes, int n_in,
                              void* d_out, int out_size) {
    const float* x  = (const float*)d_in[0];
    // d_in[1] = x0, unused (use_init=False)
    const int*   ei = (const int*)d_in[2];    // int32 (JAX x64 disabled)
    const float* Ww = (const float*)d_in[3];
    const float* Wb = (const float*)d_in[4];
    float*       out = (float*)d_out;

    int n = in_sizes[0] / F;                  // 50000
    int E = in_sizes[2] / 2;                  // 800000
    int nb = (n + 255) / 256;                 // 196 scan blocks
    if (nb > NB_MAX) nb = NB_MAX;             // defensive (n<=50000 in practice)

    k_init <<<(n + 31) / 32, 256>>>(x, Ww, n);
    k_deg  <<<(E + 255) / 256, 256>>>(ei, E);
    k_scan1<<<nb, 256>>>(n);
    k_scan2<<<1, 256>>>(nb);
    k_place<<<(E + 255) / 256, 256>>>(ei, E);
    k_gather<<<(n + 15) / 16, 256>>>(Wb, out, n);
}